// round 8
// baseline (speedup 1.0000x reference)
#include <cuda_runtime.h>
#include <math.h>

// RRN sudoku. B=16, N=64, DEG=17, H=96, 32 steps.
// Round 8: ONE persistent kernel (512 CTAs x 192 threads, all co-resident),
// software grid barrier per step, CTA-local state (Q/Ghh/s/h2/edges) in smem,
// single in-place Z buffer, 6 warps/CTA (warp = node x 32-col block).

#define NSTEP 32
#define RS 44            // Z row stride (floats). node0 rows 0..17 (17 pad), node1 rows 20..37 (37 pad)
typedef unsigned long long ull;

// ---------- device scratch (allocation-free) ----------
__device__ float g_P[2][1024 * 96];      // only cross-CTA state (double buffered)
__device__ float g_Xc[1024 * 384];
__device__ float g_Q0[1024 * 96];
__device__ float g_nodeloss[1024];
__device__ int   g_okbits[1024];
__device__ int   g_bar[NSTEP];

// ---------- packed f32x2 helpers ----------
__device__ __forceinline__ ull pack2(float x, float y) {
    ull r; asm("mov.b64 %0,{%1,%2};" : "=l"(r) : "f"(x), "f"(y)); return r;
}
__device__ __forceinline__ void unpack2(ull v, float& x, float& y) {
    asm("mov.b64 {%0,%1},%2;" : "=f"(x), "=f"(y) : "l"(v));
}
__device__ __forceinline__ void fma2(ull& d, ull a, ull b) {
    asm("fma.rn.f32x2 %0,%1,%2,%0;" : "+l"(d) : "l"(a), "l"(b));
}
__device__ __forceinline__ float sigf(float x) { return 1.f / (1.f + expf(-x)); }

// ---------- one msg layer, in place. thread = col c, node nd (9 row-pairs) ----------
__device__ __forceinline__ void kloop9(const float* ZT, ull* acc,
                                       const float* __restrict__ Wg, int c, int zbase)
{
#pragma unroll
    for (int p = 0; p < 9; p++) acc[p] = 0ull;
#pragma unroll 1
    for (int k0 = 0; k0 < 96; k0 += 8) {
        float wv[8];
#pragma unroll
        for (int u = 0; u < 8; u++) wv[u] = __ldg(Wg + (k0 + u) * 96 + c);
#pragma unroll
        for (int u = 0; u < 8; u++) {
            const float* zr = ZT + (k0 + u) * RS + zbase;
            ulonglong2 zA = *(const ulonglong2*)zr;
            ulonglong2 zB = *(const ulonglong2*)(zr + 4);
            ulonglong2 zC = *(const ulonglong2*)(zr + 8);
            ulonglong2 zD = *(const ulonglong2*)(zr + 12);
            ull        zE = *(const ull*)(zr + 16);
            ull w2 = pack2(wv[u], wv[u]);
            fma2(acc[0], zA.x, w2); fma2(acc[1], zA.y, w2);
            fma2(acc[2], zB.x, w2); fma2(acc[3], zB.y, w2);
            fma2(acc[4], zC.x, w2); fma2(acc[5], zC.y, w2);
            fma2(acc[6], zD.x, w2); fma2(acc[7], zD.y, w2);
            fma2(acc[8], zE,   w2);
        }
    }
}

// ---------- persistent kernel: CTA = 2 nodes, 192 threads, runs all 32 steps ----------
__global__ void __launch_bounds__(192, 4) rrn_persistent(
    const int* __restrict__ edges, const int* __restrict__ target,
    const float* __restrict__ msg0_W, const float* __restrict__ msg0_b,
    const float* __restrict__ msg_Ws, const float* __restrict__ msg_bs,
    const float* __restrict__ W_ih, const float* __restrict__ W_hh,
    const float* __restrict__ pred_W, const float* __restrict__ pred_b,
    float* __restrict__ d_out)
{
    __shared__ __align__(16) float ZT[96 * RS];
    __shared__ __align__(16) ull   msgd[192];   // [c*2 + nd] duplicated pairs
    __shared__ __align__(16) ull   h2d[192];    // [dim*2 + nd]
    __shared__ float sQ[192];                    // [nd*96 + c]
    __shared__ float sGhh[768];                  // [nd*384 + col]
    __shared__ float sS[192];                    // [nd*96 + dim]
    __shared__ float h2s[192];
    __shared__ float gate[768];
    __shared__ float slossa[2];
    __shared__ int   sok[2];
    __shared__ int   sedge[34];

    const int tid = threadIdx.x, lane = tid & 31, w = tid >> 5;
    const int nd = w / 3, cb = w % 3;
    const int c = cb * 32 + lane;
    const int zbase = nd * 20;
    const int n0 = blockIdx.x * 2;
    const int gd = (int)gridDim.x;

    if (tid < 34) {
        int e_nd = (tid >= 17), r = tid - 17 * e_nd;
        int j = (n0 + e_nd) & 63;
        sedge[tid] = (n0 & ~63) + __ldg(edges + j * 17 + r);
    }
    sQ[tid] = g_Q0[n0 * 96 + tid];
#pragma unroll
    for (int q = 0; q < 4; q++) sGhh[tid + 192 * q] = 0.f;
    sS[tid] = 0.f;
    if (tid < 2) { slossa[tid] = 0.f; sok[tid] = 0; }
    __syncthreads();

    for (int s = 0; s < NSTEP; s++) {
        const float* Pin  = g_P[s & 1];
        float*       Pout = g_P[(s + 1) & 1];

        // ---- gather Z0 = relu(P[edge] + Q) into this thread's column ----
        {
            float q = sQ[nd * 96 + c];
            float* z = ZT + c * RS + zbase;
            const int* se = sedge + nd * 17;
#pragma unroll
            for (int r = 0; r < 17; r++)
                z[r] = fmaxf(__ldcg(Pin + se[r] * 96 + c) + q, 0.f);
            z[17] = 0.f;
        }
        __syncthreads();

        // ---- msg layers 0,1 (relu, in place) ----
#pragma unroll 1
        for (int L = 0; L < 2; L++) {
            ull acc[9];
            kloop9(ZT, acc, msg_Ws + L * 9216, c, zbase);
            __syncthreads();
            float bv = __ldg(msg_bs + L * 96 + c);
            ull* op = (ull*)(ZT + c * RS + zbase);
#pragma unroll
            for (int p = 0; p < 9; p++) {
                float x, y; unpack2(acc[p], x, y);
                op[p] = pack2(fmaxf(x + bv, 0.f), fmaxf(y + bv, 0.f));
            }
            __syncthreads();
        }

        // ---- msg layer 2: row-sum over 17 real rows ----
        {
            ull acc[9];
            kloop9(ZT, acc, msg_Ws + 18432, c, zbase);
            float sum = 17.f * __ldg(msg_bs + 192 + c);
            float x, y;
#pragma unroll
            for (int p = 0; p < 8; p++) { unpack2(acc[p], x, y); sum += x + y; }
            unpack2(acc[8], x, y); sum += x;     // row 17 = pad, dropped
            msgd[c * 2 + nd] = pack2(sum, sum);
        }
        __syncthreads();

        // ---- gates: pair pi = tid, both nodes at once ----
        {
            const int pi = tid;
            ull a0 = 0ull, a1 = 0ull;
#pragma unroll 1
            for (int k0 = 0; k0 < 96; k0 += 8) {
                ull wp[8];
#pragma unroll
                for (int u = 0; u < 8; u++)
                    wp[u] = __ldcg((const ull*)(W_ih + (k0 + u) * 384 + 2 * pi));
#pragma unroll
                for (int u = 0; u < 8; u++) {
                    ulonglong2 m = *(const ulonglong2*)(msgd + 2 * (k0 + u));
                    fma2(a0, m.x, wp[u]);
                    fma2(a1, m.y, wp[u]);
                }
            }
            float x0, y0, x1, y1; unpack2(a0, x0, y0); unpack2(a1, x1, y1);
            float2 xc0 = __ldcg((const float2*)(g_Xc + n0 * 384 + 2 * pi));
            float2 xc1 = __ldcg((const float2*)(g_Xc + (n0 + 1) * 384 + 2 * pi));
            gate[2 * pi]           = x0 + xc0.x + sGhh[2 * pi];
            gate[2 * pi + 1]       = y0 + xc0.y + sGhh[2 * pi + 1];
            gate[384 + 2 * pi]     = x1 + xc1.x + sGhh[384 + 2 * pi];
            gate[384 + 2 * pi + 1] = y1 + xc1.y + sGhh[384 + 2 * pi + 1];
        }
        __syncthreads();

        // ---- LSTM: (node, dim) = tid ----
        {
            int ndl = tid / 96, dim = tid - 96 * ndl;
            float gi = gate[ndl * 384 + dim];
            float gf = gate[ndl * 384 + 96 + dim];
            float gg = gate[ndl * 384 + 192 + dim];
            float go = gate[ndl * 384 + 288 + dim];
            float sp = sS[tid];
            float s2 = sigf(gf) * sp + sigf(gi) * tanhf(gg);
            float h2 = sigf(go) * tanhf(s2);
            sS[tid] = s2;
            h2s[tid] = h2;
            h2d[dim * 2 + ndl] = pack2(h2, h2);
        }
        __syncthreads();

        // ---- prediction head: warp 0 = node0, warp 3 = node1 (lanes 0..7) ----
        if ((w == 0 || w == 3) && lane < 8) {
            int ndp = (w == 3) ? 1 : 0;
            int n = n0 + ndp;
            float logit = __ldg(pred_b + lane);
            const float* hr = h2s + ndp * 96;
#pragma unroll 8
            for (int k = 0; k < 96; k++)
                logit = fmaf(hr[k], __ldg(pred_W + k * 8 + lane), logit);
            const unsigned msk = 0xFFu;
            float mx = logit;
            for (int off = 4; off; off >>= 1) mx = fmaxf(mx, __shfl_xor_sync(msk, mx, off));
            float se = expf(logit - mx);
            for (int off = 4; off; off >>= 1) se += __shfl_xor_sync(msk, se, off);
            float lse = mx + logf(se);
            float bl = logit; int bc = lane;
            for (int off = 4; off; off >>= 1) {
                float ol = __shfl_xor_sync(msk, bl, off);
                int   oc = __shfl_xor_sync(msk, bc, off);
                if (ol > bl || (ol == bl && oc < bc)) { bl = ol; bc = oc; }
            }
            int tgt = __ldg(target + n) - 1;
            if (lane == tgt) slossa[ndp] += lse - logit;
            if (lane == 0) {
                sok[ndp] |= ((bc == tgt) ? 1 : 0) << s;
                if (s == NSTEP - 1) d_out[33 + n] = (float)bc;
            }
        }

        if (s == NSTEP - 1) break;

        // ---- tails for next step: Ghh (all threads), P/Q (threads 0..95) ----
        {
            const int pi = tid;
            ull a0 = 0ull, a1 = 0ull;
#pragma unroll 1
            for (int k0 = 0; k0 < 96; k0 += 8) {
                ull wp[8];
#pragma unroll
                for (int u = 0; u < 8; u++)
                    wp[u] = __ldcg((const ull*)(W_hh + (k0 + u) * 384 + 2 * pi));
#pragma unroll
                for (int u = 0; u < 8; u++) {
                    ulonglong2 h = *(const ulonglong2*)(h2d + 2 * (k0 + u));
                    fma2(a0, h.x, wp[u]);
                    fma2(a1, h.y, wp[u]);
                }
            }
            float x0, y0, x1, y1; unpack2(a0, x0, y0); unpack2(a1, x1, y1);
            sGhh[2 * pi]           = x0;
            sGhh[2 * pi + 1]       = y0;
            sGhh[384 + 2 * pi]     = x1;
            sGhh[384 + 2 * pi + 1] = y1;
        }
        if (tid < 96) {
            int isQ = (tid >= 48);
            int cp = tid - 48 * isQ;
            const float* Wp = msg0_W + (isQ ? 9216 : 0);
            ull a0 = 0ull, a1 = 0ull;
#pragma unroll 1
            for (int k0 = 0; k0 < 96; k0 += 8) {
                ull wp[8];
#pragma unroll
                for (int u = 0; u < 8; u++)
                    wp[u] = __ldcg((const ull*)(Wp + (k0 + u) * 96 + 2 * cp));
#pragma unroll
                for (int u = 0; u < 8; u++) {
                    ulonglong2 h = *(const ulonglong2*)(h2d + 2 * (k0 + u));
                    fma2(a0, h.x, wp[u]);
                    fma2(a1, h.y, wp[u]);
                }
            }
            float x0, y0, x1, y1; unpack2(a0, x0, y0); unpack2(a1, x1, y1);
            if (isQ) {
                float bx = __ldg(msg0_b + 2 * cp), by = __ldg(msg0_b + 2 * cp + 1);
                sQ[2 * cp]          = x0 + bx;
                sQ[2 * cp + 1]      = y0 + by;
                sQ[96 + 2 * cp]     = x1 + bx;
                sQ[96 + 2 * cp + 1] = y1 + by;
            } else {
                *(float2*)(Pout + n0 * 96 + 2 * cp)       = make_float2(x0, y0);
                *(float2*)(Pout + (n0 + 1) * 96 + 2 * cp) = make_float2(x1, y1);
            }
        }

        // ---- grid barrier (cross-CTA data = P only; readers use __ldcg) ----
        __threadfence_block();
        __syncthreads();
        if (tid == 0) {
            atomicAdd(&g_bar[s], 1);
            int v;
            do {
                asm volatile("ld.global.cg.s32 %0, [%1];" : "=r"(v) : "l"(g_bar + s));
                if (v < gd) __nanosleep(64);
            } while (v < gd);
        }
        __syncthreads();
    }

    __syncthreads();
    if (tid < 2) {
        g_nodeloss[n0 + tid] = slossa[tid];
        g_okbits[n0 + tid]   = sok[tid];
    }
}

// ---------- prologue: feat -> xin MLP -> Xc; init Q0, P[0], barrier counters ----------
__global__ void __launch_bounds__(128) prologue_kernel(
    const int* __restrict__ x,
    const float* __restrict__ digit_emb, const float* __restrict__ row_emb,
    const float* __restrict__ col_emb,
    const float* __restrict__ in0_W, const float* __restrict__ in0_b,
    const float* __restrict__ in_Ws, const float* __restrict__ in_bs,
    const float* __restrict__ W_ih, const float* __restrict__ b_ih,
    const float* __restrict__ b_hh, const float* __restrict__ msg0_b)
{
    __shared__ float feat[4][48], va[4][96], vb[4][96];
    int tid = threadIdx.x, lane = tid & 31, w = tid >> 5;
    int n = blockIdx.x * 4 + w;
    int j = n & 63;

    if (blockIdx.x == 0 && tid < NSTEP) g_bar[tid] = 0;

    if (lane < 16) {
        int xv = x[n];
        feat[w][lane]      = digit_emb[xv * 16 + lane];
        feat[w][16 + lane] = row_emb[(j >> 3) * 16 + lane];
        feat[w][32 + lane] = col_emb[(j & 7) * 16 + lane];
    }
    __syncwarp();

#pragma unroll
    for (int a = 0; a < 3; a++) {
        int cc = lane + 32 * a;
        float acc = in0_b[cc];
        for (int k = 0; k < 48; k++) acc = fmaf(feat[w][k], in0_W[k * 96 + cc], acc);
        va[w][cc] = fmaxf(acc, 0.f);
    }
    __syncwarp();

    for (int l = 0; l < 3; l++) {
        const float* Wl = in_Ws + l * 9216;
        const float* bl = in_bs + l * 96;
        float* src = (l == 1) ? vb[w] : va[w];
        float* dst = (l == 1) ? va[w] : vb[w];
#pragma unroll
        for (int a = 0; a < 3; a++) {
            int cc = lane + 32 * a;
            float acc = bl[cc];
            for (int k = 0; k < 96; k++) acc = fmaf(src[k], Wl[k * 96 + cc], acc);
            dst[cc] = (l < 2) ? fmaxf(acc, 0.f) : acc;
        }
        __syncwarp();
    }

    typedef unsigned long long ull_t;
    for (int pi = lane; pi < 192; pi += 32) {
        ull acc = 0ull;
#pragma unroll 4
        for (int k = 0; k < 96; k++) {
            ull w2 = __ldg((const ull_t*)(W_ih + (96 + k) * 384 + 2 * pi));
            float xk = vb[w][k];
            fma2(acc, pack2(xk, xk), w2);
        }
        float xx, yy; unpack2(acc, xx, yy);
        g_Xc[n * 384 + 2 * pi]     = xx + b_ih[2 * pi]     + b_hh[2 * pi];
        g_Xc[n * 384 + 2 * pi + 1] = yy + b_ih[2 * pi + 1] + b_hh[2 * pi + 1];
    }

    for (int t = lane; t < 96; t += 32) {
        g_P[0][n * 96 + t] = 0.f;
        g_Q0[n * 96 + t]   = msg0_b[t];
    }
}

// ---------- epilogue: reduce loss + per-step accuracy from packed okbits ----------
__global__ void __launch_bounds__(512) epilogue_kernel(float* __restrict__ d_out)
{
    __shared__ int   cnt[32];
    __shared__ float red[512];
    int tid = threadIdx.x;
    if (tid < 32) cnt[tid] = 0;
    __syncthreads();

    int s = tid >> 4, b = tid & 15;
    int ok = 1;
    for (int jj = 0; jj < 64; jj++) ok &= (g_okbits[b * 64 + jj] >> s) & 1;
    atomicAdd(&cnt[s], ok);

    float ls = 0.f;
    for (int i = tid; i < 1024; i += 512) ls += g_nodeloss[i];
    red[tid] = ls;
    __syncthreads();
    for (int off = 256; off; off >>= 1) {
        if (tid < off) red[tid] += red[tid + off];
        __syncthreads();
    }
    if (tid == 0)  d_out[0] = red[0] / (1024.f * 32.f);
    if (tid < 32)  d_out[1 + tid] = cnt[tid] * (1.f / 16.f);
}

// ---------- launch ----------
extern "C" void kernel_launch(void* const* d_in, const int* in_sizes, int n_in,
                              void* d_out, int out_size)
{
    (void)in_sizes; (void)n_in; (void)out_size;
    const int*   x         = (const int*)  d_in[0];
    const int*   target    = (const int*)  d_in[1];
    const int*   edges     = (const int*)  d_in[2];
    const float* digit_emb = (const float*)d_in[3];
    const float* row_emb   = (const float*)d_in[4];
    const float* col_emb   = (const float*)d_in[5];
    const float* in0_W     = (const float*)d_in[6];
    const float* in0_b     = (const float*)d_in[7];
    const float* in_Ws     = (const float*)d_in[8];
    const float* in_bs     = (const float*)d_in[9];
    const float* msg0_W    = (const float*)d_in[10];
    const float* msg0_b    = (const float*)d_in[11];
    const float* msg_Ws    = (const float*)d_in[12];
    const float* msg_bs    = (const float*)d_in[13];
    const float* W_ih      = (const float*)d_in[14];
    const float* W_hh      = (const float*)d_in[15];
    const float* b_ih      = (const float*)d_in[16];
    const float* b_hh      = (const float*)d_in[17];
    const float* pred_W    = (const float*)d_in[18];
    const float* pred_b    = (const float*)d_in[19];
    float* out = (float*)d_out;

    prologue_kernel<<<256, 128>>>(x, digit_emb, row_emb, col_emb,
                                  in0_W, in0_b, in_Ws, in_bs,
                                  W_ih, b_ih, b_hh, msg0_b);
    rrn_persistent<<<512, 192>>>(edges, target,
                                 msg0_W, msg0_b, msg_Ws, msg_bs,
                                 W_ih, W_hh, pred_W, pred_b, out);
    epilogue_kernel<<<1, 512>>>(out);
}